// round 1
// baseline (speedup 1.0000x reference)
#include <cuda_runtime.h>
#include <cuda_bf16.h>

#define N_NODES 100000
#define N_EDGES 500000
#define HIDDEN 32
#define HEADS 4
#define PROJ 128   // HIDDEN*HEADS
#define LN_EPS 1e-5f

// ---------------- scratch (static device globals; no runtime alloc) ----------
__device__ float g_seg[N_NODES * HIDDEN];   // folded per-node accumulator [N,32]
__device__ int   g_cnt[N_NODES];            // edge counts per destination node
__device__ float g_scoreC[HEADS * 16];      // per head: A[9], u[3], s, pad3  (all /sqrt(32))
__device__ float g_M[HIDDEN * 16];          // [d][h*4 + {mx,my,mz,c}]
__device__ int   g_is64;                    // 1 if edge_index is int64, 0 if int32

// ---------------- dtype detection for edge_index ----------------------------
// int64 little-endian values < 2^31 have every odd 32-bit word == 0.
// For genuine int32 indices in [0,100000), 256 consecutive odd slots all being
// zero has probability ~1e-1280. Reads only the first 2KB (safe either way).
__global__ void detect_kernel(const int* ei32) {
    __shared__ int nz;
    if (threadIdx.x == 0) nz = 0;
    __syncthreads();
    int v = ei32[2 * threadIdx.x + 1];
    if (v != 0) atomicAdd(&nz, 1);
    __syncthreads();
    if (threadIdx.x == 0) g_is64 = (nz == 0) ? 1 : 0;
}

// ---------------- prep: fuse weights into tiny per-edge constants ------------
// scoreC[h]: A_ij = sum_d Wq[i][h*32+d]*Wk[j][h*32+d] / sqrt(32)
//            u_i  = sum_d (Wq[i][hd]*bk[hd] + Wk[i][hd]*bq[hd]) / sqrt(32)
//            s    = sum_d bq[hd]*bk[hd] / sqrt(32)
// M[d][h*4+j]: j<3 -> sum_dd Wv[j][h*32+dd]*Wout[(h*32+dd)*32 + d]
//              j=3 -> sum_dd bv[h*32+dd]  *Wout[(h*32+dd)*32 + d]
__global__ void prep_kernel(const float* __restrict__ Wq, const float* __restrict__ bq,
                            const float* __restrict__ Wk, const float* __restrict__ bk,
                            const float* __restrict__ Wv, const float* __restrict__ bv,
                            const float* __restrict__ Wout) {
    const float invs = 0.17677669529663687f;  // 1/sqrt(32)
    int t = blockIdx.x * blockDim.x + threadIdx.x;
    if (t < 512) {
        // M entries
        int d = t >> 4;
        int idx = t & 15;
        int h = idx >> 2;
        int j = idx & 3;
        float acc = 0.f;
        if (j < 3) {
            for (int dd = 0; dd < 32; dd++)
                acc += Wv[j * PROJ + h * 32 + dd] * Wout[(h * 32 + dd) * HIDDEN + d];
        } else {
            for (int dd = 0; dd < 32; dd++)
                acc += bv[h * 32 + dd] * Wout[(h * 32 + dd) * HIDDEN + d];
        }
        g_M[t] = acc;
    } else if (t < 512 + 64) {
        int u = t - 512;
        int h = u >> 4;
        int idx = u & 15;
        float acc = 0.f;
        if (idx < 9) {
            int i = idx / 3, j = idx % 3;
            for (int d = 0; d < 32; d++)
                acc += Wq[i * PROJ + h * 32 + d] * Wk[j * PROJ + h * 32 + d];
        } else if (idx < 12) {
            int i = idx - 9;
            for (int d = 0; d < 32; d++)
                acc += Wq[i * PROJ + h * 32 + d] * bk[h * 32 + d]
                     + Wk[i * PROJ + h * 32 + d] * bq[h * 32 + d];
        } else if (idx == 12) {
            for (int d = 0; d < 32; d++)
                acc += bq[h * 32 + d] * bk[h * 32 + d];
        }
        g_scoreC[u] = acc * invs;
    }
}

// ---------------- edge kernel: scores -> softmax -> folded scatter -----------
__global__ void __launch_bounds__(256) edge_kernel(const void* __restrict__ ei_raw,
                                                   const float* __restrict__ pos) {
    __shared__ __align__(16) float sSc[64];
    __shared__ __align__(16) float sM[512];
    int t = threadIdx.x;
    if (t < 64) sSc[t] = g_scoreC[t];
    for (int i = t; i < 512; i += blockDim.x) sM[i] = g_M[i];
    __syncthreads();

    int e = blockIdx.x * blockDim.x + t;
    if (e >= N_EDGES) return;

    int row, col;
    if (g_is64) {
        const long long* ei = (const long long*)ei_raw;
        row = (int)ei[e];
        col = (int)ei[N_EDGES + e];
    } else {
        const int* ei = (const int*)ei_raw;
        row = ei[e];
        col = ei[N_EDGES + e];
    }

    float x = pos[3 * row + 0] - pos[3 * col + 0];
    float y = pos[3 * row + 1] - pos[3 * col + 1];
    float z = pos[3 * row + 2] - pos[3 * col + 2];

    // scores per head: rel^T A rel + u.rel + s   (already scaled by 1/sqrt(32))
    float sc[HEADS];
    float mx = -1e30f;
#pragma unroll
    for (int h = 0; h < HEADS; h++) {
        const float* c = &sSc[16 * h];
        float t0 = c[0] * x + c[1] * y + c[2] * z;
        float t1 = c[3] * x + c[4] * y + c[5] * z;
        float t2 = c[6] * x + c[7] * y + c[8] * z;
        float s = x * t0 + y * t1 + z * t2 + c[9] * x + c[10] * y + c[11] * z + c[12];
        sc[h] = s;
        mx = fmaxf(mx, s);
    }
    float sum = 0.f;
#pragma unroll
    for (int h = 0; h < HEADS; h++) {
        sc[h] = __expf(sc[h] - mx);
        sum += sc[h];
    }
    float inv = 1.f / sum;

    // weighted 16-vector: per head (a_h*x, a_h*y, a_h*z, a_h)
    float w[16];
#pragma unroll
    for (int h = 0; h < HEADS; h++) {
        float a = sc[h] * inv;
        w[4 * h + 0] = a * x;
        w[4 * h + 1] = a * y;
        w[4 * h + 2] = a * z;
        w[4 * h + 3] = a;
    }

    float* segp = &g_seg[(size_t)col * HIDDEN];
    const float4* sM4 = (const float4*)sM;
#pragma unroll
    for (int d4 = 0; d4 < 8; d4++) {
        float o[4];
#pragma unroll
        for (int j = 0; j < 4; j++) {
            int d = d4 * 4 + j;
            float acc = 0.f;
#pragma unroll
            for (int h = 0; h < HEADS; h++) {
                float4 m = sM4[d * 4 + h];
                acc += w[4 * h + 0] * m.x + w[4 * h + 1] * m.y
                     + w[4 * h + 2] * m.z + w[4 * h + 3] * m.w;
            }
            o[j] = acc;
        }
        asm volatile("red.global.add.v4.f32 [%0], {%1,%2,%3,%4};"
                     :: "l"(segp + d4 * 4), "f"(o[0]), "f"(o[1]), "f"(o[2]), "f"(o[3])
                     : "memory");
    }
    atomicAdd(&g_cnt[col], 1);
}

// ---------------- node kernel: mean, +bout, LayerNorm, SiLU ------------------
__global__ void __launch_bounds__(256) node_kernel(float* __restrict__ out,
                                                   const float* __restrict__ bout,
                                                   const float* __restrict__ gamma,
                                                   const float* __restrict__ beta) {
    int gtid = blockIdx.x * blockDim.x + threadIdx.x;
    int node = gtid >> 5;
    int lane = gtid & 31;
    if (node >= N_NODES) return;

    int c = g_cnt[node];
    float invc = 1.f / (float)max(c, 1);
    float v = g_seg[(size_t)node * HIDDEN + lane] * invc + bout[lane];

    float m = v;
#pragma unroll
    for (int o = 16; o > 0; o >>= 1) m += __shfl_xor_sync(0xffffffffu, m, o);
    m *= (1.f / 32.f);
    float d = v - m;
    float var = d * d;
#pragma unroll
    for (int o = 16; o > 0; o >>= 1) var += __shfl_xor_sync(0xffffffffu, var, o);
    var *= (1.f / 32.f);

    float y = d * rsqrtf(var + LN_EPS) * gamma[lane] + beta[lane];
    out[(size_t)node * HIDDEN + lane] = y / (1.f + __expf(-y));  // silu
}

// ---------------- launch ------------------------------------------------------
extern "C" void kernel_launch(void* const* d_in, const int* in_sizes, int n_in,
                              void* d_out, int out_size) {
    const float* pos  = (const float*)d_in[0];
    const void*  ei   = d_in[1];
    const float* Wq   = (const float*)d_in[2];
    const float* bq   = (const float*)d_in[3];
    const float* Wk   = (const float*)d_in[4];
    const float* bk   = (const float*)d_in[5];
    const float* Wv   = (const float*)d_in[6];
    const float* bv   = (const float*)d_in[7];
    const float* Wout = (const float*)d_in[8];
    const float* bout = (const float*)d_in[9];
    const float* gamma= (const float*)d_in[10];
    const float* beta = (const float*)d_in[11];

    void* segp = nullptr;
    void* cntp = nullptr;
    cudaGetSymbolAddress(&segp, g_seg);
    cudaGetSymbolAddress(&cntp, g_cnt);
    cudaMemsetAsync(segp, 0, sizeof(float) * N_NODES * HIDDEN, 0);
    cudaMemsetAsync(cntp, 0, sizeof(int) * N_NODES, 0);

    detect_kernel<<<1, 256>>>((const int*)ei);
    prep_kernel<<<3, 256>>>(Wq, bq, Wk, bk, Wv, bv, Wout);
    edge_kernel<<<(N_EDGES + 255) / 256, 256>>>(ei, pos);
    node_kernel<<<(N_NODES * 32 + 255) / 256, 256>>>((float*)d_out, bout, gamma, beta);
}

// round 2
// speedup vs baseline: 1.4674x; 1.4674x over previous
#include <cuda_runtime.h>
#include <cuda_bf16.h>

#define N_NODES 100000
#define N_EDGES 500000
#define HIDDEN 32
#define HEADS 4
#define PROJ 128   // HIDDEN*HEADS
#define LN_EPS 1e-5f

// ---------------- scratch (static device globals; no runtime alloc) ----------
__device__ float g_seg16[N_NODES * 16];     // per-node accumulated w-vector [N,16]
__device__ float g_scoreC[HEADS * 16];      // per head: A[9], u[3], s, pad3  (all /sqrt(32))
__device__ float g_M[HIDDEN * 16];          // [d][h*4 + {mx,my,mz,c}]  (M^T layout)
__device__ int   g_is64;                    // 1 if edge_index is int64, 0 if int32

// ---------------- prep + dtype detect (fused) --------------------------------
// blocks 0..2: fuse weights into g_M / g_scoreC
// block 3    : detect int64 vs int32 edge_index (odd 32-bit words all zero => int64)
__global__ void prep_kernel(const float* __restrict__ Wq, const float* __restrict__ bq,
                            const float* __restrict__ Wk, const float* __restrict__ bk,
                            const float* __restrict__ Wv, const float* __restrict__ bv,
                            const float* __restrict__ Wout,
                            const int* __restrict__ ei32) {
    const float invs = 0.17677669529663687f;  // 1/sqrt(32)
    if (blockIdx.x == 3) {
        __shared__ int nz;
        if (threadIdx.x == 0) nz = 0;
        __syncthreads();
        int v = ei32[2 * threadIdx.x + 1];   // first 2KB only — safe for either dtype
        if (v != 0) atomicAdd(&nz, 1);
        __syncthreads();
        if (threadIdx.x == 0) g_is64 = (nz == 0) ? 1 : 0;
        return;
    }
    int t = blockIdx.x * blockDim.x + threadIdx.x;
    if (t < 512) {
        // M^T entries: g_M[d*16 + h*4 + j]
        int d = t >> 4;
        int idx = t & 15;
        int h = idx >> 2;
        int j = idx & 3;
        float acc = 0.f;
        if (j < 3) {
            for (int dd = 0; dd < 32; dd++)
                acc += Wv[j * PROJ + h * 32 + dd] * Wout[(h * 32 + dd) * HIDDEN + d];
        } else {
            for (int dd = 0; dd < 32; dd++)
                acc += bv[h * 32 + dd] * Wout[(h * 32 + dd) * HIDDEN + d];
        }
        g_M[t] = acc;
    } else if (t < 512 + 64) {
        int u = t - 512;
        int h = u >> 4;
        int idx = u & 15;
        float acc = 0.f;
        if (idx < 9) {
            int i = idx / 3, j = idx % 3;
            for (int d = 0; d < 32; d++)
                acc += Wq[i * PROJ + h * 32 + d] * Wk[j * PROJ + h * 32 + d];
        } else if (idx < 12) {
            int i = idx - 9;
            for (int d = 0; d < 32; d++)
                acc += Wq[i * PROJ + h * 32 + d] * bk[h * 32 + d]
                     + Wk[i * PROJ + h * 32 + d] * bq[h * 32 + d];
        } else if (idx == 12) {
            for (int d = 0; d < 32; d++)
                acc += bq[h * 32 + d] * bk[h * 32 + d];
        }
        g_scoreC[u] = acc * invs;
    }
}

// ---------------- edge kernel: scores -> softmax -> 16-float scatter ----------
__global__ void __launch_bounds__(256) edge_kernel(const void* __restrict__ ei_raw,
                                                   const float* __restrict__ pos) {
    __shared__ __align__(16) float sSc[64];
    int t = threadIdx.x;
    if (t < 64) sSc[t] = g_scoreC[t];
    __syncthreads();

    int e = blockIdx.x * blockDim.x + t;
    if (e >= N_EDGES) return;

    int row, col;
    if (g_is64) {
        const long long* ei = (const long long*)ei_raw;
        row = (int)ei[e];
        col = (int)ei[N_EDGES + e];
    } else {
        const int* ei = (const int*)ei_raw;
        row = ei[e];
        col = ei[N_EDGES + e];
    }

    float x = pos[3 * row + 0] - pos[3 * col + 0];
    float y = pos[3 * row + 1] - pos[3 * col + 1];
    float z = pos[3 * row + 2] - pos[3 * col + 2];

    // scores per head: rel^T A rel + u.rel + s   (already scaled by 1/sqrt(32))
    float sc[HEADS];
    float mx = -1e30f;
#pragma unroll
    for (int h = 0; h < HEADS; h++) {
        const float* c = &sSc[16 * h];
        float t0 = c[0] * x + c[1] * y + c[2] * z;
        float t1 = c[3] * x + c[4] * y + c[5] * z;
        float t2 = c[6] * x + c[7] * y + c[8] * z;
        float s = x * t0 + y * t1 + z * t2 + c[9] * x + c[10] * y + c[11] * z + c[12];
        sc[h] = s;
        mx = fmaxf(mx, s);
    }
    float sum = 0.f;
#pragma unroll
    for (int h = 0; h < HEADS; h++) {
        sc[h] = __expf(sc[h] - mx);
        sum += sc[h];
    }
    float inv = 1.f / sum;

    // scatter per head: (a*x, a*y, a*z, a).  Count is implicit: sum_h a = 1.
    float* segp = &g_seg16[(size_t)col * 16];
#pragma unroll
    for (int h = 0; h < HEADS; h++) {
        float a = sc[h] * inv;
        asm volatile("red.global.add.v4.f32 [%0], {%1,%2,%3,%4};"
                     :: "l"(segp + 4 * h), "f"(a * x), "f"(a * y), "f"(a * z), "f"(a)
                     : "memory");
    }
}

// ---------------- node kernel: thread-per-node fold + mean + LN + SiLU -------
__global__ void __launch_bounds__(256) node_kernel(float* __restrict__ out,
                                                   const float* __restrict__ bout,
                                                   const float* __restrict__ gamma,
                                                   const float* __restrict__ beta) {
    __shared__ __align__(16) float sM[512];   // M^T: [d][16]
    __shared__ float sB[32], sG[32], sBe[32];
    int t = threadIdx.x;
    for (int i = t; i < 512; i += blockDim.x) sM[i] = g_M[i];
    if (t < 32) { sB[t] = bout[t]; sG[t] = gamma[t]; sBe[t] = beta[t]; }
    __syncthreads();

    int node = blockIdx.x * blockDim.x + t;
    if (node >= N_NODES) return;

    const float4* Wp = (const float4*)&g_seg16[(size_t)node * 16];
    float4 w0 = Wp[0], w1 = Wp[1], w2 = Wp[2], w3 = Wp[3];
    float cnt = w0.w + w1.w + w2.w + w3.w;          // = exact edge count (sum of attn=1)
    float invc = 1.f / fmaxf(cnt, 1.f);

    const float4* sM4 = (const float4*)sM;
    float o[32];
    float mean = 0.f;
#pragma unroll
    for (int d = 0; d < 32; d++) {
        float4 m0 = sM4[d * 4 + 0];
        float4 m1 = sM4[d * 4 + 1];
        float4 m2 = sM4[d * 4 + 2];
        float4 m3 = sM4[d * 4 + 3];
        float acc = w0.x * m0.x + w0.y * m0.y + w0.z * m0.z + w0.w * m0.w
                  + w1.x * m1.x + w1.y * m1.y + w1.z * m1.z + w1.w * m1.w
                  + w2.x * m2.x + w2.y * m2.y + w2.z * m2.z + w2.w * m2.w
                  + w3.x * m3.x + w3.y * m3.y + w3.z * m3.z + w3.w * m3.w;
        o[d] = acc * invc + sB[d];
        mean += o[d];
    }
    mean *= (1.f / 32.f);
    float var = 0.f;
#pragma unroll
    for (int d = 0; d < 32; d++) {
        float dd = o[d] - mean;
        var += dd * dd;
    }
    float rstd = rsqrtf(var * (1.f / 32.f) + LN_EPS);

    float4* outp = (float4*)&out[(size_t)node * 32];
#pragma unroll
    for (int d4 = 0; d4 < 8; d4++) {
        float4 r;
        float y0 = (o[d4*4+0] - mean) * rstd * sG[d4*4+0] + sBe[d4*4+0];
        float y1 = (o[d4*4+1] - mean) * rstd * sG[d4*4+1] + sBe[d4*4+1];
        float y2 = (o[d4*4+2] - mean) * rstd * sG[d4*4+2] + sBe[d4*4+2];
        float y3 = (o[d4*4+3] - mean) * rstd * sG[d4*4+3] + sBe[d4*4+3];
        r.x = y0 / (1.f + __expf(-y0));
        r.y = y1 / (1.f + __expf(-y1));
        r.z = y2 / (1.f + __expf(-y2));
        r.w = y3 / (1.f + __expf(-y3));
        outp[d4] = r;
    }
}

// ---------------- launch ------------------------------------------------------
extern "C" void kernel_launch(void* const* d_in, const int* in_sizes, int n_in,
                              void* d_out, int out_size) {
    const float* pos  = (const float*)d_in[0];
    const void*  ei   = d_in[1];
    const float* Wq   = (const float*)d_in[2];
    const float* bq   = (const float*)d_in[3];
    const float* Wk   = (const float*)d_in[4];
    const float* bk   = (const float*)d_in[5];
    const float* Wv   = (const float*)d_in[6];
    const float* bv   = (const float*)d_in[7];
    const float* Wout = (const float*)d_in[8];
    const float* bout = (const float*)d_in[9];
    const float* gamma= (const float*)d_in[10];
    const float* beta = (const float*)d_in[11];

    void* segp = nullptr;
    cudaGetSymbolAddress(&segp, g_seg16);
    cudaMemsetAsync(segp, 0, sizeof(float) * N_NODES * 16, 0);

    prep_kernel<<<4, 256>>>(Wq, bq, Wk, bk, Wv, bv, Wout, (const int*)ei);
    edge_kernel<<<(N_EDGES + 255) / 256, 256>>>(ei, pos);
    node_kernel<<<(N_NODES + 255) / 256, 256>>>((float*)d_out, bout, gamma, beta);
}